// round 15
// baseline (speedup 1.0000x reference)
#include <cuda_runtime.h>
#include <cuda_fp16.h>
#include <cstdint>

#define VOCAB 32000
#define HID   128
#define BATCH 4
#define SEQT  2048
#define BT    (BATCH*SEQT)
#define CH    32
#define NCH   (SEQT/CH)

#define BM 128
#define BN 256
#define NMB (BT/BM)
#define NNB (VOCAB/BN)
#define ROWB 272
#define A_TILE (128*ROWB)            // 34816
#define B_TILE (256*ROWB)            // 69632
#define OFF_A 1024
#define OFF_B (OFF_A + A_TILE)       // 35840
#define FC_SMEM (OFF_B + B_TILE)     // 105472  -> 2 CTAs/SM

// ---------------- scratch ----------------
__device__ __align__(16) float g_c0[BT*HID + 2*HID];
__device__ __align__(16) float g_c1[BT*HID + 2*HID];
__device__ __align__(16) float g_h0[BT*HID];
__device__ __align__(16) __half g_yhi[BT*HID];
__device__ __align__(16) __half g_whi[VOCAB*HID];
__device__ int g_prog0[BATCH];
__device__ int g_flag1[BATCH*NCH];

// ---------------- sync helpers ----------------
__device__ __forceinline__ int ld_acq(const int* p) {
    int v;
    asm volatile("ld.acquire.gpu.global.s32 %0, [%1];" : "=r"(v) : "l"(p) : "memory");
    return v;
}
__device__ __forceinline__ void st_rel(int* p, int v) {
    asm volatile("st.release.gpu.global.s32 [%0], %1;" :: "l"(p), "r"(v) : "memory");
}

// ---------------- flag reset ----------------
__global__ void reset_kernel() {
    const int tid = threadIdx.x;
    if (tid < BATCH) g_prog0[tid] = 0;
    for (int i = tid; i < BATCH*NCH; i += 32) g_flag1[i] = 0;
}

// ---------------- prolog: proj0 (256 CTAs) + fc_w -> fp16 (128 CTAs) ----------------
__global__ __launch_bounds__(128) void prolog_kernel(
    const void* __restrict__ xin, const float* __restrict__ emb,
    const float* __restrict__ W, const float* __restrict__ ba,
    const float* __restrict__ bb, const float* __restrict__ fcw)
{
    const int bid = blockIdx.x;
    const int j   = threadIdx.x;

    if (bid < 256) {
        __shared__ float sx[32][HID];
        __shared__ int s_is64;
        const int chunk = bid;

        if (j == 0) {
            const int* x32 = (const int*)xin;
            int acc = 0;
            #pragma unroll
            for (int i = 0; i < 64; i++) acc |= x32[2*i + 1];
            s_is64 = (acc == 0) ? 1 : 0;
        }

        float w[HID];
        #pragma unroll
        for (int k = 0; k < HID; k += 4) {
            float4 v = *(const float4*)(W + j*HID + k);
            w[k] = v.x; w[k+1] = v.y; w[k+2] = v.z; w[k+3] = v.w;
        }
        __syncthreads();

        const int is64 = s_is64;
        for (int r = 0; r < 32; r++) {
            int bt = chunk*32 + r;
            long long idx = is64 ? ((const long long*)xin)[bt]
                                 : (long long)((const int*)xin)[bt];
            sx[r][j] = emb[idx*HID + j];
        }
        __syncthreads();

        const float bias = ba[j] + bb[j];
        for (int r = 0; r < 32; r++) {
            float acc = bias;
            #pragma unroll
            for (int k = 0; k < HID; k++) acc += w[k] * sx[r][k];
            g_c0[(chunk*32 + r)*HID + j] = acc;
        }
    } else {
        for (int i = (bid - 256)*128 + j; i < VOCAB*HID; i += 128*128)
            g_whi[i] = __float2half_rn(fcw[i]);
    }
}

// ---------------- math helpers ----------------
__device__ __forceinline__ float fast_tanh(float s) {
    float ax = fabsf(s);
    float e  = __expf(-2.0f * ax);
    float th = __fdividef(1.0f - e, 1.0f + e);
    return copysignf(th, s);
}
__device__ __forceinline__ float dot128s(const float* w, const float* hs) {
    const float4* hb = (const float4*)hs;
    float a0=0,a1=0,a2=0,a3=0,a4=0,a5=0,a6=0,a7=0;
    #pragma unroll
    for (int k = 0; k < 8; k++) {
        float4 q0 = hb[k], q1 = hb[k+8], q2 = hb[k+16], q3 = hb[k+24];
        a0 += w[4*k+0]*q0.x;    a1 += w[4*k+1]*q0.y;
        a2 += w[4*k+2]*q0.z;    a3 += w[4*k+3]*q0.w;
        a4 += w[32+4*k+0]*q1.x; a5 += w[32+4*k+1]*q1.y;
        a6 += w[32+4*k+2]*q1.z; a7 += w[32+4*k+3]*q1.w;
        a0 += w[64+4*k+0]*q2.x; a1 += w[64+4*k+1]*q2.y;
        a2 += w[64+4*k+2]*q2.z; a3 += w[64+4*k+3]*q2.w;
        a4 += w[96+4*k+0]*q3.x; a5 += w[96+4*k+1]*q3.y;
        a6 += w[96+4*k+2]*q3.z; a7 += w[96+4*k+3]*q3.w;
    }
    return ((a0+a1)+(a2+a3)) + ((a4+a5)+(a6+a7));
}
__device__ __forceinline__ float dot128g(const float* w, const float4* hr) {
    float a0=0,a1=0,a2=0,a3=0,a4=0,a5=0,a6=0,a7=0;
    #pragma unroll
    for (int k = 0; k < 8; k++) {
        float4 q0 = __ldg(hr+k), q1 = __ldg(hr+k+8),
               q2 = __ldg(hr+k+16), q3 = __ldg(hr+k+24);
        a0 += w[4*k+0]*q0.x;    a1 += w[4*k+1]*q0.y;
        a2 += w[4*k+2]*q0.z;    a3 += w[4*k+3]*q0.w;
        a4 += w[32+4*k+0]*q1.x; a5 += w[32+4*k+1]*q1.y;
        a6 += w[32+4*k+2]*q1.z; a7 += w[32+4*k+3]*q1.w;
        a0 += w[64+4*k+0]*q2.x; a1 += w[64+4*k+1]*q2.y;
        a2 += w[64+4*k+2]*q2.z; a3 += w[64+4*k+3]*q2.w;
        a4 += w[96+4*k+0]*q3.x; a5 += w[96+4*k+1]*q3.y;
        a6 += w[96+4*k+2]*q3.z; a7 += w[96+4*k+3]*q3.w;
    }
    return ((a0+a1)+(a2+a3)) + ((a4+a5)+(a6+a7));
}

// ---------------- pipe: 40 CTAs x 128 threads (R14-proven, unchanged) ----------------
__global__ __launch_bounds__(128, 1) void pipe_kernel(
    const float* __restrict__ Whh0, const float* __restrict__ Wih1,
    const float* __restrict__ Whh1,
    const float* __restrict__ bih1, const float* __restrict__ bhh1,
    const float* __restrict__ hidden, float* __restrict__ hout)
{
    const int bid = blockIdx.x;
    const int j   = threadIdx.x;
    __shared__ __align__(16) float sh[2][HID];

    if (bid < 4) {
        const int b = bid;
        float w[HID];
        #pragma unroll
        for (int k = 0; k < HID; k += 4) {
            float4 v = *(const float4*)(Whh0 + j*HID + k);
            w[k] = v.x; w[k+1] = v.y; w[k+2] = v.z; w[k+3] = v.w;
        }
        sh[0][j] = hidden[b*HID + j];
        __syncthreads();

        const float* cb = g_c0 + (size_t)b*SEQT*HID;
        float cp0 = cb[j], cp1 = cb[HID + j];

        for (int t = 0; t < SEQT; t++) {
            const float cc = cp0;
            cp0 = cp1;
            cp1 = __ldg(&cb[(size_t)(t+2)*HID + j]);

            float s  = cc + dot128s(w, sh[t & 1]);
            float hn = fast_tanh(s);
            sh[(t+1) & 1][j] = hn;
            g_h0[(size_t)(b*SEQT + t)*HID + j] = hn;
            __syncthreads();
            if (((t+1) & (CH-1)) == 0 && j == 0)
                st_rel(&g_prog0[b], t + 1);
        }
        hout[b*HID + j] = sh[SEQT & 1][j];

    } else if (bid < 36) {
        const int wi = bid - 4;
        const int b  = wi >> 3;
        float w[HID];
        #pragma unroll
        for (int k = 0; k < HID; k += 4) {
            float4 v = *(const float4*)(Wih1 + j*HID + k);
            w[k] = v.x; w[k+1] = v.y; w[k+2] = v.z; w[k+3] = v.w;
        }
        const float bias = bih1[j] + bhh1[j];

        for (int k = (wi & 7); k < NCH; k += 8) {
            if (j == 0) {
                const int target = (k + 1) * CH;
                while (ld_acq(&g_prog0[b]) < target) __nanosleep(128);
            }
            __syncthreads();
            for (int t = k*CH; t < (k+1)*CH; t++) {
                const size_t bt = (size_t)(b*SEQT + t);
                g_c1[bt*HID + j] = bias +
                    dot128g(w, (const float4*)(g_h0 + bt*HID));
            }
            __syncthreads();
            if (j == 0) st_rel(&g_flag1[b*NCH + k], 1);
        }

    } else {
        const int b = bid - 36;
        float w[HID];
        #pragma unroll
        for (int k = 0; k < HID; k += 4) {
            float4 v = *(const float4*)(Whh1 + j*HID + k);
            w[k] = v.x; w[k+1] = v.y; w[k+2] = v.z; w[k+3] = v.w;
        }
        sh[0][j] = hidden[(BATCH + b)*HID + j];
        if (j == 0) {
            while (ld_acq(&g_flag1[b*NCH + 0]) == 0) __nanosleep(128);
            while (ld_acq(&g_flag1[b*NCH + 1]) == 0) __nanosleep(128);
        }
        __syncthreads();

        const float* cb = g_c1 + (size_t)b*SEQT*HID;
        float cp0 = cb[j], cp1 = cb[HID + j];

        for (int t = 0; t < SEQT; t++) {
            if ((t & (CH-1)) == 0 && t > 0) {
                if (j == 0) {
                    const int kn = min((t >> 5) + 1, NCH - 1);
                    while (ld_acq(&g_flag1[b*NCH + kn]) == 0) __nanosleep(128);
                }
                __syncthreads();
            }
            const float cc = cp0;
            cp0 = cp1;
            cp1 = __ldg(&cb[(size_t)(t+2)*HID + j]);

            float s  = cc + dot128s(w, sh[t & 1]);
            float hn = fast_tanh(s);
            sh[(t+1) & 1][j] = hn;
            g_yhi[(size_t)(b*SEQT + t)*HID + j] = __float2half_rn(hn);
            __syncthreads();
        }
        hout[(BATCH + b)*HID + j] = sh[SEQT & 1][j];
    }
}

// ---------------- fc GEMM: SINGLE-pass fp16 (logits = yhi . whi + b) ----------------
__device__ __forceinline__ void ldsm_x4(uint32_t addr, uint32_t& r0, uint32_t& r1,
                                        uint32_t& r2, uint32_t& r3) {
    asm volatile("ldmatrix.sync.aligned.m8n8.x4.shared.b16 {%0,%1,%2,%3}, [%4];"
                 : "=r"(r0), "=r"(r1), "=r"(r2), "=r"(r3) : "r"(addr));
}
__device__ __forceinline__ void mma16816(float* c, uint32_t a0, uint32_t a1,
                                         uint32_t a2, uint32_t a3,
                                         uint32_t b0, uint32_t b1) {
    asm volatile("mma.sync.aligned.m16n8k16.row.col.f32.f16.f16.f32 "
        "{%0,%1,%2,%3}, {%4,%5,%6,%7}, {%8,%9}, {%0,%1,%2,%3};"
        : "+f"(c[0]), "+f"(c[1]), "+f"(c[2]), "+f"(c[3])
        : "r"(a0), "r"(a1), "r"(a2), "r"(a3), "r"(b0), "r"(b1));
}

__global__ __launch_bounds__(512, 2) void fc_kernel(const float* __restrict__ fcb,
                                                    float* __restrict__ out) {
    extern __shared__ char sm[];
    const int tid = threadIdx.x;
    const int n0 = blockIdx.x * BN;
    const int m0 = blockIdx.y * BM;

    if (tid < 256) ((float*)sm)[tid] = fcb[n0 + tid];

    for (int i = tid; i < 128*16; i += 512) {
        int r = i >> 4, c = i & 15;
        *(uint4*)(sm + OFF_A + r*ROWB + c*16) =
            ((const uint4*)(g_yhi + (size_t)(m0+r)*HID))[c];
    }
    for (int i = tid; i < 256*16; i += 512) {
        int r = i >> 4, c = i & 15;
        *(uint4*)(sm + OFF_B + r*ROWB + c*16) =
            ((const uint4*)(g_whi + (size_t)(n0+r)*HID))[c];
    }
    __syncthreads();

    const int lane = tid & 31, wid = tid >> 5;
    const int wm = wid >> 2, wn = wid & 3;
    const uint32_t smem_base = (uint32_t)__cvta_generic_to_shared(sm);

    const uint32_t a_base = smem_base + OFF_A + (wm*32 + (lane & 15))*ROWB + (lane >> 4)*16;
    const uint32_t b_base = smem_base + OFF_B + (wn*64 + (lane & 15))*ROWB + (lane >> 4)*16;

    float acc[2][8][4];
    #pragma unroll
    for (int mi = 0; mi < 2; mi++)
        #pragma unroll
        for (int ni = 0; ni < 8; ni++)
            #pragma unroll
            for (int q = 0; q < 4; q++) acc[mi][ni][q] = 0.f;

    #pragma unroll
    for (int k0 = 0; k0 < 8; k0++) {
        const uint32_t kb = k0*32;
        uint32_t a[2][4];
        ldsm_x4(a_base + kb,            a[0][0], a[0][1], a[0][2], a[0][3]);
        ldsm_x4(a_base + 16*ROWB + kb,  a[1][0], a[1][1], a[1][2], a[1][3]);
        uint32_t bfr[8][2];
        #pragma unroll
        for (int np = 0; np < 4; np++) {
            uint32_t r0, r1, r2, r3;
            ldsm_x4(b_base + np*(16*ROWB) + kb, r0, r1, r2, r3);
            bfr[2*np][0]   = r0; bfr[2*np][1]   = r2;
            bfr[2*np+1][0] = r1; bfr[2*np+1][1] = r3;
        }
        #pragma unroll
        for (int mi = 0; mi < 2; mi++)
            #pragma unroll
            for (int ni = 0; ni < 8; ni++)
                mma16816(acc[mi][ni], a[mi][0], a[mi][1], a[mi][2], a[mi][3],
                         bfr[ni][0], bfr[ni][1]);
    }

    const float* bias = (const float*)sm;
    const int r_lo = m0 + wm*32 + (lane >> 2);
    #pragma unroll
    for (int mi = 0; mi < 2; mi++) {
        #pragma unroll
        for (int ni = 0; ni < 8; ni++) {
            const int col = wn*64 + ni*8 + (lane & 3)*2;
            const float b0 = bias[col], b1 = bias[col + 1];
            float2 v0 = make_float2(acc[mi][ni][0] + b0, acc[mi][ni][1] + b1);
            float2 v1 = make_float2(acc[mi][ni][2] + b0, acc[mi][ni][3] + b1);
            *(float2*)(out + (size_t)(r_lo + mi*16    )*VOCAB + n0 + col) = v0;
            *(float2*)(out + (size_t)(r_lo + mi*16 + 8)*VOCAB + n0 + col) = v1;
        }
    }
}

// ---------------- launch ----------------
extern "C" void kernel_launch(void* const* d_in, const int* in_sizes, int n_in,
                              void* d_out, int out_size) {
    const void*  x      = d_in[0];
    const float* hidden = (const float*)d_in[1];
    const float* emb    = (const float*)d_in[2];
    const float* W_ih0  = (const float*)d_in[3];
    const float* W_hh0  = (const float*)d_in[4];
    const float* b_ih0  = (const float*)d_in[5];
    const float* b_hh0  = (const float*)d_in[6];
    const float* W_ih1  = (const float*)d_in[7];
    const float* W_hh1  = (const float*)d_in[8];
    const float* b_ih1  = (const float*)d_in[9];
    const float* b_hh1  = (const float*)d_in[10];
    const float* fc_w   = (const float*)d_in[11];
    const float* fc_b   = (const float*)d_in[12];
    float* out = (float*)d_out;
    float* out_hidden = out + (size_t)BT * VOCAB;

    reset_kernel<<<1, 32>>>();
    prolog_kernel<<<384, 128>>>(x, emb, W_ih0, b_ih0, b_hh0, fc_w);
    pipe_kernel<<<40, 128>>>(W_hh0, W_ih1, W_hh1, b_ih1, b_hh1,
                             hidden, out_hidden);

    cudaFuncSetAttribute(fc_kernel, cudaFuncAttributeMaxDynamicSharedMemorySize, FC_SMEM);
    fc_kernel<<<dim3(NNB, NMB), 512, FC_SMEM>>>(fc_b, out);
}

// round 16
// speedup vs baseline: 1.2566x; 1.2566x over previous
#include <cuda_runtime.h>
#include <cuda_fp16.h>
#include <cstdint>

#define VOCAB 32000
#define HID   128
#define BATCH 4
#define SEQT  2048
#define BT    (BATCH*SEQT)
#define CH    32
#define NCH   (SEQT/CH)

#define BM 128
#define BN 256
#define NMB (BT/BM)
#define NNB (VOCAB/BN)
#define ROWB 272
#define A_TILE (128*ROWB)            // 34816
#define B_TILE (256*ROWB)            // 69632
#define OFF_A 1024
#define OFF_B (OFF_A + A_TILE)       // 35840
#define FC_SMEM (OFF_B + B_TILE)     // 105472

// ---------------- scratch ----------------
__device__ __align__(16) float g_c0[BT*HID + 2*HID];
__device__ __align__(16) float g_c1[BT*HID + 2*HID];
__device__ __align__(16) float g_h0[BT*HID];
__device__ __align__(16) __half g_yhi[BT*HID];
__device__ __align__(16) __half g_whi[VOCAB*HID];
__device__ int g_prog0[BATCH];
__device__ int g_flag1[BATCH*NCH];

// ---------------- sync helpers ----------------
__device__ __forceinline__ int ld_acq(const int* p) {
    int v;
    asm volatile("ld.acquire.gpu.global.s32 %0, [%1];" : "=r"(v) : "l"(p) : "memory");
    return v;
}
__device__ __forceinline__ void st_rel(int* p, int v) {
    asm volatile("st.release.gpu.global.s32 [%0], %1;" :: "l"(p), "r"(v) : "memory");
}

// ---------------- flag reset ----------------
__global__ void reset_kernel() {
    const int tid = threadIdx.x;
    if (tid < BATCH) g_prog0[tid] = 0;
    for (int i = tid; i < BATCH*NCH; i += 32) g_flag1[i] = 0;
}

// ---------------- prolog: proj0 (256 CTAs) + fc_w -> fp16 (128 CTAs) ----------------
__global__ __launch_bounds__(128) void prolog_kernel(
    const void* __restrict__ xin, const float* __restrict__ emb,
    const float* __restrict__ W, const float* __restrict__ ba,
    const float* __restrict__ bb, const float* __restrict__ fcw)
{
    const int bid = blockIdx.x;
    const int j   = threadIdx.x;

    if (bid < 256) {
        __shared__ float sx[32][HID];
        __shared__ int s_is64;
        const int chunk = bid;

        if (j == 0) {
            const int* x32 = (const int*)xin;
            int acc = 0;
            #pragma unroll
            for (int i = 0; i < 64; i++) acc |= x32[2*i + 1];
            s_is64 = (acc == 0) ? 1 : 0;
        }

        float w[HID];
        #pragma unroll
        for (int k = 0; k < HID; k += 4) {
            float4 v = *(const float4*)(W + j*HID + k);
            w[k] = v.x; w[k+1] = v.y; w[k+2] = v.z; w[k+3] = v.w;
        }
        __syncthreads();

        const int is64 = s_is64;
        for (int r = 0; r < 32; r++) {
            int bt = chunk*32 + r;
            long long idx = is64 ? ((const long long*)xin)[bt]
                                 : (long long)((const int*)xin)[bt];
            sx[r][j] = emb[idx*HID + j];
        }
        __syncthreads();

        const float bias = ba[j] + bb[j];
        for (int r = 0; r < 32; r++) {
            float acc = bias;
            #pragma unroll
            for (int k = 0; k < HID; k++) acc += w[k] * sx[r][k];
            g_c0[(chunk*32 + r)*HID + j] = acc;
        }
    } else {
        for (int i = (bid - 256)*128 + j; i < VOCAB*HID; i += 128*128)
            g_whi[i] = __float2half_rn(fcw[i]);
    }
}

// ---------------- math helpers ----------------
__device__ __forceinline__ float fast_tanh(float s) {
    float ax = fabsf(s);
    float e  = __expf(-2.0f * ax);
    float th = __fdividef(1.0f - e, 1.0f + e);
    return copysignf(th, s);
}
__device__ __forceinline__ float dot128s(const float* w, const float* hs) {
    const float4* hb = (const float4*)hs;
    float a0=0,a1=0,a2=0,a3=0,a4=0,a5=0,a6=0,a7=0;
    #pragma unroll
    for (int k = 0; k < 8; k++) {
        float4 q0 = hb[k], q1 = hb[k+8], q2 = hb[k+16], q3 = hb[k+24];
        a0 += w[4*k+0]*q0.x;    a1 += w[4*k+1]*q0.y;
        a2 += w[4*k+2]*q0.z;    a3 += w[4*k+3]*q0.w;
        a4 += w[32+4*k+0]*q1.x; a5 += w[32+4*k+1]*q1.y;
        a6 += w[32+4*k+2]*q1.z; a7 += w[32+4*k+3]*q1.w;
        a0 += w[64+4*k+0]*q2.x; a1 += w[64+4*k+1]*q2.y;
        a2 += w[64+4*k+2]*q2.z; a3 += w[64+4*k+3]*q2.w;
        a4 += w[96+4*k+0]*q3.x; a5 += w[96+4*k+1]*q3.y;
        a6 += w[96+4*k+2]*q3.z; a7 += w[96+4*k+3]*q3.w;
    }
    return ((a0+a1)+(a2+a3)) + ((a4+a5)+(a6+a7));
}
__device__ __forceinline__ float dot128g(const float* w, const float4* hr) {
    float a0=0,a1=0,a2=0,a3=0,a4=0,a5=0,a6=0,a7=0;
    #pragma unroll
    for (int k = 0; k < 8; k++) {
        float4 q0 = __ldg(hr+k), q1 = __ldg(hr+k+8),
               q2 = __ldg(hr+k+16), q3 = __ldg(hr+k+24);
        a0 += w[4*k+0]*q0.x;    a1 += w[4*k+1]*q0.y;
        a2 += w[4*k+2]*q0.z;    a3 += w[4*k+3]*q0.w;
        a4 += w[32+4*k+0]*q1.x; a5 += w[32+4*k+1]*q1.y;
        a6 += w[32+4*k+2]*q1.z; a7 += w[32+4*k+3]*q1.w;
        a0 += w[64+4*k+0]*q2.x; a1 += w[64+4*k+1]*q2.y;
        a2 += w[64+4*k+2]*q2.z; a3 += w[64+4*k+3]*q2.w;
        a4 += w[96+4*k+0]*q3.x; a5 += w[96+4*k+1]*q3.y;
        a6 += w[96+4*k+2]*q3.z; a7 += w[96+4*k+3]*q3.w;
    }
    return ((a0+a1)+(a2+a3)) + ((a4+a5)+(a6+a7));
}

// ---------------- pipe: 40 CTAs x 128 threads (R14-proven, unchanged) ----------------
__global__ __launch_bounds__(128, 1) void pipe_kernel(
    const float* __restrict__ Whh0, const float* __restrict__ Wih1,
    const float* __restrict__ Whh1,
    const float* __restrict__ bih1, const float* __restrict__ bhh1,
    const float* __restrict__ hidden, float* __restrict__ hout)
{
    const int bid = blockIdx.x;
    const int j   = threadIdx.x;
    __shared__ __align__(16) float sh[2][HID];

    if (bid < 4) {
        const int b = bid;
        float w[HID];
        #pragma unroll
        for (int k = 0; k < HID; k += 4) {
            float4 v = *(const float4*)(Whh0 + j*HID + k);
            w[k] = v.x; w[k+1] = v.y; w[k+2] = v.z; w[k+3] = v.w;
        }
        sh[0][j] = hidden[b*HID + j];
        __syncthreads();

        const float* cb = g_c0 + (size_t)b*SEQT*HID;
        float cp0 = cb[j], cp1 = cb[HID + j];

        for (int t = 0; t < SEQT; t++) {
            const float cc = cp0;
            cp0 = cp1;
            cp1 = __ldg(&cb[(size_t)(t+2)*HID + j]);

            float s  = cc + dot128s(w, sh[t & 1]);
            float hn = fast_tanh(s);
            sh[(t+1) & 1][j] = hn;
            g_h0[(size_t)(b*SEQT + t)*HID + j] = hn;
            __syncthreads();
            if (((t+1) & (CH-1)) == 0 && j == 0)
                st_rel(&g_prog0[b], t + 1);
        }
        hout[b*HID + j] = sh[SEQT & 1][j];

    } else if (bid < 36) {
        const int wi = bid - 4;
        const int b  = wi >> 3;
        float w[HID];
        #pragma unroll
        for (int k = 0; k < HID; k += 4) {
            float4 v = *(const float4*)(Wih1 + j*HID + k);
            w[k] = v.x; w[k+1] = v.y; w[k+2] = v.z; w[k+3] = v.w;
        }
        const float bias = bih1[j] + bhh1[j];

        for (int k = (wi & 7); k < NCH; k += 8) {
            if (j == 0) {
                const int target = (k + 1) * CH;
                while (ld_acq(&g_prog0[b]) < target) __nanosleep(128);
            }
            __syncthreads();
            for (int t = k*CH; t < (k+1)*CH; t++) {
                const size_t bt = (size_t)(b*SEQT + t);
                g_c1[bt*HID + j] = bias +
                    dot128g(w, (const float4*)(g_h0 + bt*HID));
            }
            __syncthreads();
            if (j == 0) st_rel(&g_flag1[b*NCH + k], 1);
        }

    } else {
        const int b = bid - 36;
        float w[HID];
        #pragma unroll
        for (int k = 0; k < HID; k += 4) {
            float4 v = *(const float4*)(Whh1 + j*HID + k);
            w[k] = v.x; w[k+1] = v.y; w[k+2] = v.z; w[k+3] = v.w;
        }
        sh[0][j] = hidden[(BATCH + b)*HID + j];
        if (j == 0) {
            while (ld_acq(&g_flag1[b*NCH + 0]) == 0) __nanosleep(128);
            while (ld_acq(&g_flag1[b*NCH + 1]) == 0) __nanosleep(128);
        }
        __syncthreads();

        const float* cb = g_c1 + (size_t)b*SEQT*HID;
        float cp0 = cb[j], cp1 = cb[HID + j];

        for (int t = 0; t < SEQT; t++) {
            if ((t & (CH-1)) == 0 && t > 0) {
                if (j == 0) {
                    const int kn = min((t >> 5) + 1, NCH - 1);
                    while (ld_acq(&g_flag1[b*NCH + kn]) == 0) __nanosleep(128);
                }
                __syncthreads();
            }
            const float cc = cp0;
            cp0 = cp1;
            cp1 = __ldg(&cb[(size_t)(t+2)*HID + j]);

            float s  = cc + dot128s(w, sh[t & 1]);
            float hn = fast_tanh(s);
            sh[(t+1) & 1][j] = hn;
            g_yhi[(size_t)(b*SEQT + t)*HID + j] = __float2half_rn(hn);
            __syncthreads();
        }
        hout[(BATCH + b)*HID + j] = sh[SEQT & 1][j];
    }
}

// ---------------- fc GEMM: single-pass fp16, NO min-blocks cap (regs ~128) ----------------
__device__ __forceinline__ void ldsm_x4(uint32_t addr, uint32_t& r0, uint32_t& r1,
                                        uint32_t& r2, uint32_t& r3) {
    asm volatile("ldmatrix.sync.aligned.m8n8.x4.shared.b16 {%0,%1,%2,%3}, [%4];"
                 : "=r"(r0), "=r"(r1), "=r"(r2), "=r"(r3) : "r"(addr));
}
__device__ __forceinline__ void mma16816(float* c, uint32_t a0, uint32_t a1,
                                         uint32_t a2, uint32_t a3,
                                         uint32_t b0, uint32_t b1) {
    asm volatile("mma.sync.aligned.m16n8k16.row.col.f32.f16.f16.f32 "
        "{%0,%1,%2,%3}, {%4,%5,%6,%7}, {%8,%9}, {%0,%1,%2,%3};"
        : "+f"(c[0]), "+f"(c[1]), "+f"(c[2]), "+f"(c[3])
        : "r"(a0), "r"(a1), "r"(a2), "r"(a3), "r"(b0), "r"(b1));
}

__global__ __launch_bounds__(512) void fc_kernel(const float* __restrict__ fcb,
                                                 float* __restrict__ out) {
    extern __shared__ char sm[];
    const int tid = threadIdx.x;
    const int n0 = blockIdx.x * BN;
    const int m0 = blockIdx.y * BM;

    if (tid < 256) ((float*)sm)[tid] = fcb[n0 + tid];

    for (int i = tid; i < 128*16; i += 512) {
        int r = i >> 4, c = i & 15;
        *(uint4*)(sm + OFF_A + r*ROWB + c*16) =
            ((const uint4*)(g_yhi + (size_t)(m0+r)*HID))[c];
    }
    for (int i = tid; i < 256*16; i += 512) {
        int r = i >> 4, c = i & 15;
        *(uint4*)(sm + OFF_B + r*ROWB + c*16) =
            ((const uint4*)(g_whi + (size_t)(n0+r)*HID))[c];
    }
    __syncthreads();

    const int lane = tid & 31, wid = tid >> 5;
    const int wm = wid >> 2, wn = wid & 3;
    const uint32_t smem_base = (uint32_t)__cvta_generic_to_shared(sm);

    const uint32_t a_base = smem_base + OFF_A + (wm*32 + (lane & 15))*ROWB + (lane >> 4)*16;
    const uint32_t b_base = smem_base + OFF_B + (wn*64 + (lane & 15))*ROWB + (lane >> 4)*16;

    float acc[2][8][4];
    #pragma unroll
    for (int mi = 0; mi < 2; mi++)
        #pragma unroll
        for (int ni = 0; ni < 8; ni++)
            #pragma unroll
            for (int q = 0; q < 4; q++) acc[mi][ni][q] = 0.f;

    #pragma unroll
    for (int k0 = 0; k0 < 8; k0++) {
        const uint32_t kb = k0*32;
        uint32_t a[2][4];
        ldsm_x4(a_base + kb,            a[0][0], a[0][1], a[0][2], a[0][3]);
        ldsm_x4(a_base + 16*ROWB + kb,  a[1][0], a[1][1], a[1][2], a[1][3]);
        uint32_t bfr[8][2];
        #pragma unroll
        for (int np = 0; np < 4; np++) {
            uint32_t r0, r1, r2, r3;
            ldsm_x4(b_base + np*(16*ROWB) + kb, r0, r1, r2, r3);
            bfr[2*np][0]   = r0; bfr[2*np][1]   = r2;
            bfr[2*np+1][0] = r1; bfr[2*np+1][1] = r3;
        }
        #pragma unroll
        for (int mi = 0; mi < 2; mi++)
            #pragma unroll
            for (int ni = 0; ni < 8; ni++)
                mma16816(acc[mi][ni], a[mi][0], a[mi][1], a[mi][2], a[mi][3],
                         bfr[ni][0], bfr[ni][1]);
    }

    const float* bias = (const float*)sm;
    const int r_lo = m0 + wm*32 + (lane >> 2);
    #pragma unroll
    for (int mi = 0; mi < 2; mi++) {
        #pragma unroll
        for (int ni = 0; ni < 8; ni++) {
            const int col = wn*64 + ni*8 + (lane & 3)*2;
            const float b0 = bias[col], b1 = bias[col + 1];
            float2 v0 = make_float2(acc[mi][ni][0] + b0, acc[mi][ni][1] + b1);
            float2 v1 = make_float2(acc[mi][ni][2] + b0, acc[mi][ni][3] + b1);
            *(float2*)(out + (size_t)(r_lo + mi*16    )*VOCAB + n0 + col) = v0;
            *(float2*)(out + (size_t)(r_lo + mi*16 + 8)*VOCAB + n0 + col) = v1;
        }
    }
}

// ---------------- launch ----------------
extern "C" void kernel_launch(void* const* d_in, const int* in_sizes, int n_in,
                              void* d_out, int out_size) {
    const void*  x      = d_in[0];
    const float* hidden = (const float*)d_in[1];
    const float* emb    = (const float*)d_in[2];
    const float* W_ih0  = (const float*)d_in[3];
    const float* W_hh0  = (const float*)d_in[4];
    const float* b_ih0  = (const float*)d_in[5];
    const float* b_hh0  = (const float*)d_in[6];
    const float* W_ih1  = (const float*)d_in[7];
    const float* W_hh1  = (const float*)d_in[8];
    const float* b_ih1  = (const float*)d_in[9];
    const float* b_hh1  = (const float*)d_in[10];
    const float* fc_w   = (const float*)d_in[11];
    const float* fc_b   = (const float*)d_in[12];
    float* out = (float*)d_out;
    float* out_hidden = out + (size_t)BT * VOCAB;

    reset_kernel<<<1, 32>>>();
    prolog_kernel<<<384, 128>>>(x, emb, W_ih0, b_ih0, b_hh0, fc_w);
    pipe_kernel<<<40, 128>>>(W_hh0, W_ih1, W_hh1, b_ih1, b_hh1,
                             hidden, out_hidden);

    cudaFuncSetAttribute(fc_kernel, cudaFuncAttributeMaxDynamicSharedMemorySize, FC_SMEM);
    fc_kernel<<<dim3(NNB, NMB), 512, FC_SMEM>>>(fc_b, out);
}

// round 17
// speedup vs baseline: 1.3435x; 1.0691x over previous
#include <cuda_runtime.h>
#include <cuda_fp16.h>
#include <cstdint>

#define VOCAB 32000
#define HID   128
#define BATCH 4
#define SEQT  2048
#define BT    (BATCH*SEQT)
#define CH    32
#define NCH   (SEQT/CH)

#define BM 128
#define BN 128
#define NMB (BT/BM)                  // 64
#define NNB (VOCAB/BN)               // 250
#define ROWB 272
#define A_TILE (128*ROWB)            // 34816
#define B_TILE (128*ROWB)            // 34816
#define OFF_A 1024
#define OFF_B (OFF_A + A_TILE)       // 35840
#define FC_SMEM (OFF_B + B_TILE)     // 70656  -> 2 CTAs/SM (reg-capped)

// ---------------- scratch ----------------
__device__ __align__(16) float g_c0[BT*HID + 2*HID];
__device__ __align__(16) float g_c1[BT*HID + 2*HID];
__device__ __align__(16) float g_h0[BT*HID];
__device__ __align__(16) __half g_yhi[BT*HID];
__device__ __align__(16) __half g_whi[VOCAB*HID];
__device__ int g_prog0[BATCH];
__device__ int g_flag1[BATCH*NCH];

// ---------------- sync helpers ----------------
__device__ __forceinline__ int ld_acq(const int* p) {
    int v;
    asm volatile("ld.acquire.gpu.global.s32 %0, [%1];" : "=r"(v) : "l"(p) : "memory");
    return v;
}
__device__ __forceinline__ void st_rel(int* p, int v) {
    asm volatile("st.release.gpu.global.s32 [%0], %1;" :: "l"(p), "r"(v) : "memory");
}

// ---------------- flag reset ----------------
__global__ void reset_kernel() {
    const int tid = threadIdx.x;
    if (tid < BATCH) g_prog0[tid] = 0;
    for (int i = tid; i < BATCH*NCH; i += 32) g_flag1[i] = 0;
}

// ---------------- prolog: proj0 (256 CTAs) + fc_w -> fp16 (128 CTAs) ----------------
__global__ __launch_bounds__(128) void prolog_kernel(
    const void* __restrict__ xin, const float* __restrict__ emb,
    const float* __restrict__ W, const float* __restrict__ ba,
    const float* __restrict__ bb, const float* __restrict__ fcw)
{
    const int bid = blockIdx.x;
    const int j   = threadIdx.x;

    if (bid < 256) {
        __shared__ float sx[32][HID];
        __shared__ int s_is64;
        const int chunk = bid;

        if (j == 0) {
            const int* x32 = (const int*)xin;
            int acc = 0;
            #pragma unroll
            for (int i = 0; i < 64; i++) acc |= x32[2*i + 1];
            s_is64 = (acc == 0) ? 1 : 0;
        }

        float w[HID];
        #pragma unroll
        for (int k = 0; k < HID; k += 4) {
            float4 v = *(const float4*)(W + j*HID + k);
            w[k] = v.x; w[k+1] = v.y; w[k+2] = v.z; w[k+3] = v.w;
        }
        __syncthreads();

        const int is64 = s_is64;
        for (int r = 0; r < 32; r++) {
            int bt = chunk*32 + r;
            long long idx = is64 ? ((const long long*)xin)[bt]
                                 : (long long)((const int*)xin)[bt];
            sx[r][j] = emb[idx*HID + j];
        }
        __syncthreads();

        const float bias = ba[j] + bb[j];
        for (int r = 0; r < 32; r++) {
            float acc = bias;
            #pragma unroll
            for (int k = 0; k < HID; k++) acc += w[k] * sx[r][k];
            g_c0[(chunk*32 + r)*HID + j] = acc;
        }
    } else {
        for (int i = (bid - 256)*128 + j; i < VOCAB*HID; i += 128*128)
            g_whi[i] = __float2half_rn(fcw[i]);
    }
}

// ---------------- math helpers ----------------
__device__ __forceinline__ float fast_tanh(float s) {
    float ax = fabsf(s);
    float e  = __expf(-2.0f * ax);
    float th = __fdividef(1.0f - e, 1.0f + e);
    return copysignf(th, s);
}
__device__ __forceinline__ float dot128s(const float* w, const float* hs) {
    const float4* hb = (const float4*)hs;
    float a0=0,a1=0,a2=0,a3=0,a4=0,a5=0,a6=0,a7=0;
    #pragma unroll
    for (int k = 0; k < 8; k++) {
        float4 q0 = hb[k], q1 = hb[k+8], q2 = hb[k+16], q3 = hb[k+24];
        a0 += w[4*k+0]*q0.x;    a1 += w[4*k+1]*q0.y;
        a2 += w[4*k+2]*q0.z;    a3 += w[4*k+3]*q0.w;
        a4 += w[32+4*k+0]*q1.x; a5 += w[32+4*k+1]*q1.y;
        a6 += w[32+4*k+2]*q1.z; a7 += w[32+4*k+3]*q1.w;
        a0 += w[64+4*k+0]*q2.x; a1 += w[64+4*k+1]*q2.y;
        a2 += w[64+4*k+2]*q2.z; a3 += w[64+4*k+3]*q2.w;
        a4 += w[96+4*k+0]*q3.x; a5 += w[96+4*k+1]*q3.y;
        a6 += w[96+4*k+2]*q3.z; a7 += w[96+4*k+3]*q3.w;
    }
    return ((a0+a1)+(a2+a3)) + ((a4+a5)+(a6+a7));
}
__device__ __forceinline__ float dot128g(const float* w, const float4* hr) {
    float a0=0,a1=0,a2=0,a3=0,a4=0,a5=0,a6=0,a7=0;
    #pragma unroll
    for (int k = 0; k < 8; k++) {
        float4 q0 = __ldg(hr+k), q1 = __ldg(hr+k+8),
               q2 = __ldg(hr+k+16), q3 = __ldg(hr+k+24);
        a0 += w[4*k+0]*q0.x;    a1 += w[4*k+1]*q0.y;
        a2 += w[4*k+2]*q0.z;    a3 += w[4*k+3]*q0.w;
        a4 += w[32+4*k+0]*q1.x; a5 += w[32+4*k+1]*q1.y;
        a6 += w[32+4*k+2]*q1.z; a7 += w[32+4*k+3]*q1.w;
        a0 += w[64+4*k+0]*q2.x; a1 += w[64+4*k+1]*q2.y;
        a2 += w[64+4*k+2]*q2.z; a3 += w[64+4*k+3]*q2.w;
        a4 += w[96+4*k+0]*q3.x; a5 += w[96+4*k+1]*q3.y;
        a6 += w[96+4*k+2]*q3.z; a7 += w[96+4*k+3]*q3.w;
    }
    return ((a0+a1)+(a2+a3)) + ((a4+a5)+(a6+a7));
}

// ---------------- pipe: 40 CTAs x 128 threads (R14-proven, unchanged) ----------------
__global__ __launch_bounds__(128, 1) void pipe_kernel(
    const float* __restrict__ Whh0, const float* __restrict__ Wih1,
    const float* __restrict__ Whh1,
    const float* __restrict__ bih1, const float* __restrict__ bhh1,
    const float* __restrict__ hidden, float* __restrict__ hout)
{
    const int bid = blockIdx.x;
    const int j   = threadIdx.x;
    __shared__ __align__(16) float sh[2][HID];

    if (bid < 4) {
        const int b = bid;
        float w[HID];
        #pragma unroll
        for (int k = 0; k < HID; k += 4) {
            float4 v = *(const float4*)(Whh0 + j*HID + k);
            w[k] = v.x; w[k+1] = v.y; w[k+2] = v.z; w[k+3] = v.w;
        }
        sh[0][j] = hidden[b*HID + j];
        __syncthreads();

        const float* cb = g_c0 + (size_t)b*SEQT*HID;
        float cp0 = cb[j], cp1 = cb[HID + j];

        for (int t = 0; t < SEQT; t++) {
            const float cc = cp0;
            cp0 = cp1;
            cp1 = __ldg(&cb[(size_t)(t+2)*HID + j]);

            float s  = cc + dot128s(w, sh[t & 1]);
            float hn = fast_tanh(s);
            sh[(t+1) & 1][j] = hn;
            g_h0[(size_t)(b*SEQT + t)*HID + j] = hn;
            __syncthreads();
            if (((t+1) & (CH-1)) == 0 && j == 0)
                st_rel(&g_prog0[b], t + 1);
        }
        hout[b*HID + j] = sh[SEQT & 1][j];

    } else if (bid < 36) {
        const int wi = bid - 4;
        const int b  = wi >> 3;
        float w[HID];
        #pragma unroll
        for (int k = 0; k < HID; k += 4) {
            float4 v = *(const float4*)(Wih1 + j*HID + k);
            w[k] = v.x; w[k+1] = v.y; w[k+2] = v.z; w[k+3] = v.w;
        }
        const float bias = bih1[j] + bhh1[j];

        for (int k = (wi & 7); k < NCH; k += 8) {
            if (j == 0) {
                const int target = (k + 1) * CH;
                while (ld_acq(&g_prog0[b]) < target) __nanosleep(128);
            }
            __syncthreads();
            for (int t = k*CH; t < (k+1)*CH; t++) {
                const size_t bt = (size_t)(b*SEQT + t);
                g_c1[bt*HID + j] = bias +
                    dot128g(w, (const float4*)(g_h0 + bt*HID));
            }
            __syncthreads();
            if (j == 0) st_rel(&g_flag1[b*NCH + k], 1);
        }

    } else {
        const int b = bid - 36;
        float w[HID];
        #pragma unroll
        for (int k = 0; k < HID; k += 4) {
            float4 v = *(const float4*)(Whh1 + j*HID + k);
            w[k] = v.x; w[k+1] = v.y; w[k+2] = v.z; w[k+3] = v.w;
        }
        sh[0][j] = hidden[(BATCH + b)*HID + j];
        if (j == 0) {
            while (ld_acq(&g_flag1[b*NCH + 0]) == 0) __nanosleep(128);
            while (ld_acq(&g_flag1[b*NCH + 1]) == 0) __nanosleep(128);
        }
        __syncthreads();

        const float* cb = g_c1 + (size_t)b*SEQT*HID;
        float cp0 = cb[j], cp1 = cb[HID + j];

        for (int t = 0; t < SEQT; t++) {
            if ((t & (CH-1)) == 0 && t > 0) {
                if (j == 0) {
                    const int kn = min((t >> 5) + 1, NCH - 1);
                    while (ld_acq(&g_flag1[b*NCH + kn]) == 0) __nanosleep(128);
                }
                __syncthreads();
            }
            const float cc = cp0;
            cp0 = cp1;
            cp1 = __ldg(&cb[(size_t)(t+2)*HID + j]);

            float s  = cc + dot128s(w, sh[t & 1]);
            float hn = fast_tanh(s);
            sh[(t+1) & 1][j] = hn;
            g_yhi[(size_t)(b*SEQT + t)*HID + j] = __float2half_rn(hn);
            __syncthreads();
        }
        hout[(BATCH + b)*HID + j] = sh[SEQT & 1][j];
    }
}

// ---------------- fc GEMM: single-pass fp16, 128x128 tile, 256 thr, 2 CTAs/SM ----------------
__device__ __forceinline__ void ldsm_x4(uint32_t addr, uint32_t& r0, uint32_t& r1,
                                        uint32_t& r2, uint32_t& r3) {
    asm volatile("ldmatrix.sync.aligned.m8n8.x4.shared.b16 {%0,%1,%2,%3}, [%4];"
                 : "=r"(r0), "=r"(r1), "=r"(r2), "=r"(r3) : "r"(addr));
}
__device__ __forceinline__ void mma16816(float* c, uint32_t a0, uint32_t a1,
                                         uint32_t a2, uint32_t a3,
                                         uint32_t b0, uint32_t b1) {
    asm volatile("mma.sync.aligned.m16n8k16.row.col.f32.f16.f16.f32 "
        "{%0,%1,%2,%3}, {%4,%5,%6,%7}, {%8,%9}, {%0,%1,%2,%3};"
        : "+f"(c[0]), "+f"(c[1]), "+f"(c[2]), "+f"(c[3])
        : "r"(a0), "r"(a1), "r"(a2), "r"(a3), "r"(b0), "r"(b1));
}

__global__ __launch_bounds__(256, 2) void fc_kernel(const float* __restrict__ fcb,
                                                    float* __restrict__ out) {
    extern __shared__ char sm[];
    const int tid = threadIdx.x;
    const int n0 = blockIdx.x * BN;
    const int m0 = blockIdx.y * BM;

    if (tid < 128) ((float*)sm)[tid] = fcb[n0 + tid];

    for (int i = tid; i < 128*16; i += 256) {
        int r = i >> 4, c = i & 15;
        *(uint4*)(sm + OFF_A + r*ROWB + c*16) =
            ((const uint4*)(g_yhi + (size_t)(m0+r)*HID))[c];
        *(uint4*)(sm + OFF_B + r*ROWB + c*16) =
            ((const uint4*)(g_whi + (size_t)(n0+r)*HID))[c];
    }
    __syncthreads();

    const int lane = tid & 31, wid = tid >> 5;
    const int wm = wid >> 1, wn = wid & 1;         // 4x2 warps, warp tile 32m x 64n
    const uint32_t smem_base = (uint32_t)__cvta_generic_to_shared(sm);

    const uint32_t a_base = smem_base + OFF_A + (wm*32 + (lane & 15))*ROWB + (lane >> 4)*16;
    const uint32_t b_base = smem_base + OFF_B + (wn*64 + (lane & 15))*ROWB + (lane >> 4)*16;

    float acc[2][8][4];
    #pragma unroll
    for (int mi = 0; mi < 2; mi++)
        #pragma unroll
        for (int ni = 0; ni < 8; ni++)
            #pragma unroll
            for (int q = 0; q < 4; q++) acc[mi][ni][q] = 0.f;

    #pragma unroll
    for (int k0 = 0; k0 < 8; k0++) {
        const uint32_t kb = k0*32;
        uint32_t a[2][4];
        ldsm_x4(a_base + kb,            a[0][0], a[0][1], a[0][2], a[0][3]);
        ldsm_x4(a_base + 16*ROWB + kb,  a[1][0], a[1][1], a[1][2], a[1][3]);
        uint32_t bfr[8][2];
        #pragma unroll
        for (int np = 0; np < 4; np++) {
            uint32_t r0, r1, r2, r3;
            ldsm_x4(b_base + np*(16*ROWB) + kb, r0, r1, r2, r3);
            bfr[2*np][0]   = r0; bfr[2*np][1]   = r2;
            bfr[2*np+1][0] = r1; bfr[2*np+1][1] = r3;
        }
        #pragma unroll
        for (int mi = 0; mi < 2; mi++)
            #pragma unroll
            for (int ni = 0; ni < 8; ni++)
                mma16816(acc[mi][ni], a[mi][0], a[mi][1], a[mi][2], a[mi][3],
                         bfr[ni][0], bfr[ni][1]);
    }

    const float* bias = (const float*)sm;
    const int r_lo = m0 + wm*32 + (lane >> 2);
    #pragma unroll
    for (int mi = 0; mi < 2; mi++) {
        #pragma unroll
        for (int ni = 0; ni < 8; ni++) {
            const int col = wn*64 + ni*8 + (lane & 3)*2;
            const float b0 = bias[col], b1 = bias[col + 1];
            float2 v0 = make_float2(acc[mi][ni][0] + b0, acc[mi][ni][1] + b1);
            float2 v1 = make_float2(acc[mi][ni][2] + b0, acc[mi][ni][3] + b1);
            *(float2*)(out + (size_t)(r_lo + mi*16    )*VOCAB + n0 + col) = v0;
            *(float2*)(out + (size_t)(r_lo + mi*16 + 8)*VOCAB + n0 + col) = v1;
        }
    }
}

// ---------------- launch ----------------
extern "C" void kernel_launch(void* const* d_in, const int* in_sizes, int n_in,
                              void* d_out, int out_size) {
    const void*  x      = d_in[0];
    const float* hidden = (const float*)d_in[1];
    const float* emb    = (const float*)d_in[2];
    const float* W_ih0  = (const float*)d_in[3];
    const float* W_hh0  = (const float*)d_in[4];
    const float* b_ih0  = (const float*)d_in[5];
    const float* b_hh0  = (const float*)d_in[6];
    const float* W_ih1  = (const float*)d_in[7];
    const float* W_hh1  = (const float*)d_in[8];
    const float* b_ih1  = (const float*)d_in[9];
    const float* b_hh1  = (const float*)d_in[10];
    const float* fc_w   = (const float*)d_in[11];
    const float* fc_b   = (const float*)d_in[12];
    float* out = (float*)d_out;
    float* out_hidden = out + (size_t)BT * VOCAB;

    reset_kernel<<<1, 32>>>();
    prolog_kernel<<<384, 128>>>(x, emb, W_ih0, b_ih0, b_hh0, fc_w);
    pipe_kernel<<<40, 128>>>(W_hh0, W_ih1, W_hh1, b_ih1, b_hh1,
                             hidden, out_hidden);

    cudaFuncSetAttribute(fc_kernel, cudaFuncAttributeMaxDynamicSharedMemorySize, FC_SMEM);
    fc_kernel<<<dim3(NNB, NMB), 256, FC_SMEM>>>(fc_b, out);
}